// round 14
// baseline (speedup 1.0000x reference)
#include <cuda_runtime.h>
#include <cstdint>

#define MAX_NODES 100000
#define MAX_EDGES 1600000
#define IN_C  32
#define HID_C 64
#define OUT_C 32
#define NT 128
#define STRIDE 132
#define SCAN_CHUNK 1024
#define MAX_CHUNKS 128

// Scratch (__device__ globals: allocation-free rule)
__device__ __align__(16) float g_agg1[MAX_NODES * IN_C];   // raw sums
__device__ __align__(16) float g_hw  [MAX_NODES * OUT_C];  // relu(h) @ W2_l
__device__ int g_deg   [MAX_NODES];
__device__ int g_rowptr[MAX_NODES + 1];
__device__ int g_cursor[MAX_NODES];
__device__ int g_col   [MAX_EDGES];
__device__ int g_chunkSum[MAX_CHUNKS];

// ---------------------------------------------------------------------------
// Packed f32x2 helpers (Blackwell FFMA2)
// ---------------------------------------------------------------------------
__device__ __forceinline__ void fma2(unsigned long long& d,
                                     unsigned long long a,
                                     unsigned long long b)
{
    asm("fma.rn.f32x2 %0, %1, %2, %0;" : "+l"(d) : "l"(a), "l"(b));
}
__device__ __forceinline__ unsigned long long pack2(float v)
{
    unsigned long long r;
    asm("mov.b64 %0, {%1, %1};" : "=l"(r) : "r"(__float_as_uint(v)));
    return r;
}
__device__ __forceinline__ float2 unpack2(unsigned long long v)
{
    float2 f;
    asm("mov.b64 {%0, %1}, %2;" : "=f"(f.x), "=f"(f.y) : "l"(v));
    return f;
}

// ---------------------------------------------------------------------------
// Layer-1 warp-shuffle scatter (no cnt atomics; deg comes from CSR rowptr)
// ---------------------------------------------------------------------------
__global__ void scatter32(const float* __restrict__ feat,
                          const int* __restrict__ ei,
                          float* __restrict__ agg,
                          int n_edges)
{
    int warp = (blockIdx.x * blockDim.x + threadIdx.x) >> 5;
    int lane = threadIdx.x & 31;
    int base = warp * 32;
    if (base >= n_edges) return;

    int my_e   = base + lane;
    int e_clmp = (my_e < n_edges) ? my_e : (n_edges - 1);
    int my_src = __ldg(ei + e_clmp);
    int my_dst = __ldg(ei + n_edges + e_clmp);

    int seg = lane & 7;
    int sub = lane >> 3;

#pragma unroll
    for (int pass = 0; pass < 8; pass++) {
        int eslot = pass * 4 + sub;
        int src = __shfl_sync(0xffffffffu, my_src, eslot);
        int dst = __shfl_sync(0xffffffffu, my_dst, eslot);
        if (base + eslot < n_edges) {
            float4 v = *(const float4*)(feat + (long long)src * 32 + seg * 4);
            atomicAdd((float4*)(agg + (long long)dst * 32 + seg * 4), v);
        }
    }
}

// ---------------------------------------------------------------------------
// CSR build
// ---------------------------------------------------------------------------
__global__ void deg_count(const int* __restrict__ dst, int* __restrict__ deg,
                          int n_edges)
{
    int e = blockIdx.x * blockDim.x + threadIdx.x;
    if (e < n_edges) atomicAdd(&deg[dst[e]], 1);
}

__global__ void scan1(const int* __restrict__ deg, int* __restrict__ pref,
                      int* __restrict__ chunkSum, int n)
{
    __shared__ int sT[256];
    int chunk = blockIdx.x;
    int base  = chunk * SCAN_CHUNK;
    int t     = threadIdx.x;

    int v[4], s = 0;
#pragma unroll
    for (int j = 0; j < 4; j++) {
        int idx = base + t * 4 + j;
        v[j] = (idx < n) ? deg[idx] : 0;
        s += v[j];
    }
    sT[t] = s;
    __syncthreads();
#pragma unroll
    for (int off = 1; off < 256; off <<= 1) {
        int y = (t >= off) ? sT[t - off] : 0;
        __syncthreads();
        sT[t] += y;
        __syncthreads();
    }
    int excl = sT[t] - s;
#pragma unroll
    for (int j = 0; j < 4; j++) {
        int idx = base + t * 4 + j;
        if (idx < n) pref[idx] = excl;
        excl += v[j];
    }
    if (t == 255) chunkSum[chunk] = sT[255];
}

__global__ void scan2b(int* __restrict__ rowptr, int* __restrict__ cursor,
                       const int* __restrict__ chunkSum, int n, int nchunks)
{
    __shared__ int sCS[MAX_CHUNKS];
    for (int j = threadIdx.x; j < nchunks; j += blockDim.x)
        sCS[j] = chunkSum[j];
    __syncthreads();

    int i = blockIdx.x * blockDim.x + threadIdx.x;
    if (i < n) {
        int myChunk = i / SCAN_CHUNK;
        int off = 0;
        for (int j = 0; j < myChunk; j++) off += sCS[j];
        int v = rowptr[i] + off;
        rowptr[i] = v;
        cursor[i] = v;
    }
    if (i == 0) {
        int tot = 0;
        for (int j = 0; j < nchunks; j++) tot += sCS[j];
        rowptr[n] = tot;
    }
}

__global__ void csr_fill(const int* __restrict__ src, const int* __restrict__ dst,
                         int* __restrict__ cursor, int* __restrict__ col,
                         int n_edges)
{
    int e = blockIdx.x * blockDim.x + threadIdx.x;
    if (e >= n_edges) return;
    int d = dst[e];
    int pos = atomicAdd(&cursor[d], 1);
    col[pos] = src[e];
}

// ---------------------------------------------------------------------------
// CSR gather, C=32, fused final combine: out[n,:] += sum(hw[col])/max(deg,1)
// (out pre-initialized with b2 + hr by the transform)
// ---------------------------------------------------------------------------
__global__ __launch_bounds__(256)
void gather32_fused(const float* __restrict__ feat,
                    const int* __restrict__ rowptr,
                    const int* __restrict__ col,
                    float* __restrict__ outp,
                    int n_nodes)
{
    int node = (blockIdx.x * blockDim.x + threadIdx.x) >> 5;
    int lane = threadIdx.x & 31;
    if (node >= n_nodes) return;

    int beg = rowptr[node];
    int end = rowptr[node + 1];

    int sub = lane >> 3;
    int seg = lane & 7;

    float4 acc = {0.f, 0.f, 0.f, 0.f};
    for (int i = beg; i < end; i += 8) {
        int cv = (lane < 8 && i + lane < end) ? __ldg(col + i + lane) : 0;
        int c0 = __shfl_sync(0xffffffffu, cv, sub);
        int c1 = __shfl_sync(0xffffffffu, cv, 4 + sub);
        bool p0 = (i + sub) < end;
        bool p1 = (i + 4 + sub) < end;
        float4 v0 = {0,0,0,0}, v1 = {0,0,0,0};
        if (p0) v0 = *(const float4*)(feat + (long long)c0 * 32 + seg * 4);
        if (p1) v1 = *(const float4*)(feat + (long long)c1 * 32 + seg * 4);
        acc.x += v0.x + v1.x; acc.y += v0.y + v1.y;
        acc.z += v0.z + v1.z; acc.w += v0.w + v1.w;
    }
#pragma unroll
    for (int off = 8; off < 32; off <<= 1) {
        acc.x += __shfl_xor_sync(0xffffffffu, acc.x, off);
        acc.y += __shfl_xor_sync(0xffffffffu, acc.y, off);
        acc.z += __shfl_xor_sync(0xffffffffu, acc.z, off);
        acc.w += __shfl_xor_sync(0xffffffffu, acc.w, off);
    }
    if (lane < 8) {
        float inv = 1.0f / fmaxf((float)(end - beg), 1.0f);
        float* dstp = outp + (long long)node * 32 + seg * 4;
        float4 prev = *(const float4*)dstp;
        float4 o;
        o.x = acc.x * inv + prev.x;
        o.y = acc.y * inv + prev.y;
        o.z = acc.z * inv + prev.z;
        o.w = acc.w * inv + prev.w;
        *(float4*)dstp = o;
    }
}

// ---------------------------------------------------------------------------
// Tiled fused transform (R11/R13 structure; deg from rowptr)
// ---------------------------------------------------------------------------
__global__ __launch_bounds__(256)
void transform_l1_tiled(const float* __restrict__ x,
                        const float* __restrict__ agg,
                        const int* __restrict__ rowptr,
                        const float* __restrict__ W1l,
                        const float* __restrict__ b1,
                        const float* __restrict__ W1r,
                        const float* __restrict__ W2l,
                        const float* __restrict__ b2,
                        const float* __restrict__ W2r,
                        float* __restrict__ hw,
                        float* __restrict__ outp,
                        int n_nodes)
{
    extern __shared__ __align__(16) float smem[];
    float* sAgg = smem;
    float* sX   = smem + IN_C * STRIDE;
    float* sH   = smem;                          // overlay
    float* sW1l = smem + HID_C * STRIDE;
    float* sW1r = sW1l + IN_C * HID_C;
    float* sW2  = sW1r + IN_C * HID_C;           // [W2l | W2r]
    float* sB   = sW2  + HID_C * 64;
    float* sB2  = sB   + HID_C;

    int tid  = threadIdx.x;
    int warp = tid >> 5;
    int lane = tid & 31;

    for (int i = tid * 4; i < IN_C * HID_C; i += 256 * 4) {
        *(float4*)&sW1l[i] = *(const float4*)&W1l[i];
        *(float4*)&sW1r[i] = *(const float4*)&W1r[i];
    }
    for (int i = tid * 4; i < HID_C * 64; i += 256 * 4) {
        int k = i >> 6, c = i & 63;
        float4 v = (c < 32) ? *(const float4*)&W2l[k * OUT_C + c]
                            : *(const float4*)&W2r[k * OUT_C + (c - 32)];
        *(float4*)&sW2[i] = v;
    }
    if (tid < HID_C) sB[tid] = b1[tid];
    if (tid < OUT_C) sB2[tid] = b2[tid];

    int nodeBase = blockIdx.x * NT;
    for (int i = tid; i < NT * 8; i += 256) {
        int node = i >> 3, kc = i & 7;
        int ng = nodeBase + node;
        float4 a = {0,0,0,0}, xv = {0,0,0,0};
        float inv = 0.0f;
        if (ng < n_nodes) {
            int deg = rowptr[ng + 1] - rowptr[ng];
            inv = 1.0f / fmaxf((float)deg, 1.0f);
            a  = *(const float4*)(agg + (long long)ng * IN_C + kc * 4);
            xv = *(const float4*)(x   + (long long)ng * IN_C + kc * 4);
        }
        int kb = kc * 4;
        sAgg[(kb + 0) * STRIDE + node] = a.x * inv;
        sAgg[(kb + 1) * STRIDE + node] = a.y * inv;
        sAgg[(kb + 2) * STRIDE + node] = a.z * inv;
        sAgg[(kb + 3) * STRIDE + node] = a.w * inv;
        sX  [(kb + 0) * STRIDE + node] = xv.x;
        sX  [(kb + 1) * STRIDE + node] = xv.y;
        sX  [(kb + 2) * STRIDE + node] = xv.z;
        sX  [(kb + 3) * STRIDE + node] = xv.w;
    }
    __syncthreads();

    const int cb = warp * 8;
    const int nb = lane * 4;

    unsigned long long acc[4][4];
#pragma unroll
    for (int n = 0; n < 4; n++)
#pragma unroll
        for (int p = 0; p < 4; p++) acc[n][p] = 0ull;

#pragma unroll
    for (int k = 0; k < IN_C; k++) {
        float4 av = *(const float4*)&sAgg[k * STRIDE + nb];
        float4 xv = *(const float4*)&sX  [k * STRIDE + nb];
        ulonglong2 wl0 = *(const ulonglong2*)&sW1l[k * HID_C + cb];
        ulonglong2 wl1 = *(const ulonglong2*)&sW1l[k * HID_C + cb + 4];
        ulonglong2 wr0 = *(const ulonglong2*)&sW1r[k * HID_C + cb];
        ulonglong2 wr1 = *(const ulonglong2*)&sW1r[k * HID_C + cb + 4];
        float avf[4] = {av.x, av.y, av.z, av.w};
        float xvf[4] = {xv.x, xv.y, xv.z, xv.w};
#pragma unroll
        for (int n = 0; n < 4; n++) {
            unsigned long long a2 = pack2(avf[n]);
            fma2(acc[n][0], a2, wl0.x); fma2(acc[n][1], a2, wl0.y);
            fma2(acc[n][2], a2, wl1.x); fma2(acc[n][3], a2, wl1.y);
            unsigned long long x2 = pack2(xvf[n]);
            fma2(acc[n][0], x2, wr0.x); fma2(acc[n][1], x2, wr0.y);
            fma2(acc[n][2], x2, wr1.x); fma2(acc[n][3], x2, wr1.y);
        }
    }
    __syncthreads();

#pragma unroll
    for (int c = 0; c < 8; c += 2) {
        float2 p0 = unpack2(acc[0][c / 2]);
        float2 p1 = unpack2(acc[1][c / 2]);
        float2 p2 = unpack2(acc[2][c / 2]);
        float2 p3 = unpack2(acc[3][c / 2]);
        float b0 = sB[cb + c], b1v = sB[cb + c + 1];
        float4 v0 = {fmaxf(p0.x + b0, 0.f), fmaxf(p1.x + b0, 0.f),
                     fmaxf(p2.x + b0, 0.f), fmaxf(p3.x + b0, 0.f)};
        float4 v1 = {fmaxf(p0.y + b1v, 0.f), fmaxf(p1.y + b1v, 0.f),
                     fmaxf(p2.y + b1v, 0.f), fmaxf(p3.y + b1v, 0.f)};
        *(float4*)&sH[(cb + c)     * STRIDE + nb] = v0;
        *(float4*)&sH[(cb + c + 1) * STRIDE + nb] = v1;
    }
    __syncthreads();

    unsigned long long acc2[4][4];
#pragma unroll
    for (int n = 0; n < 4; n++)
#pragma unroll
        for (int p = 0; p < 4; p++) acc2[n][p] = 0ull;

#pragma unroll 8
    for (int k = 0; k < HID_C; k++) {
        float4 hv = *(const float4*)&sH[k * STRIDE + nb];
        ulonglong2 w0 = *(const ulonglong2*)&sW2[k * 64 + cb];
        ulonglong2 w1 = *(const ulonglong2*)&sW2[k * 64 + cb + 4];
        float hvf[4] = {hv.x, hv.y, hv.z, hv.w};
#pragma unroll
        for (int n = 0; n < 4; n++) {
            unsigned long long h2 = pack2(hvf[n]);
            fma2(acc2[n][0], h2, w0.x); fma2(acc2[n][1], h2, w0.y);
            fma2(acc2[n][2], h2, w1.x); fma2(acc2[n][3], h2, w1.y);
        }
    }

    bool to_out = (cb >= 32);
    float* basep = to_out ? outp : hw;
    int coff = to_out ? cb - 32 : cb;
    float add[8];
#pragma unroll
    for (int j = 0; j < 8; j++) add[j] = to_out ? sB2[coff + j] : 0.f;
#pragma unroll
    for (int n = 0; n < 4; n++) {
        int node = nodeBase + nb + n;
        if (node < n_nodes) {
            float2 q0 = unpack2(acc2[n][0]);
            float2 q1 = unpack2(acc2[n][1]);
            float2 q2 = unpack2(acc2[n][2]);
            float2 q3 = unpack2(acc2[n][3]);
            float4 o0 = {q0.x + add[0], q0.y + add[1], q1.x + add[2], q1.y + add[3]};
            float4 o1 = {q2.x + add[4], q2.y + add[5], q3.x + add[6], q3.y + add[7]};
            *(float4*)(basep + (long long)node * OUT_C + coff)     = o0;
            *(float4*)(basep + (long long)node * OUT_C + coff + 4) = o1;
        }
    }
}

// ---------------------------------------------------------------------------
// Launch: fork-join — stream B runs scatter1 while default stream builds CSR.
// Streams/events created once on the first (uncaptured correctness) call.
// ---------------------------------------------------------------------------
struct Aux {
    cudaStream_t s;
    cudaEvent_t fork, join;
    Aux() {
        cudaStreamCreateWithFlags(&s, cudaStreamNonBlocking);
        cudaEventCreateWithFlags(&fork, cudaEventDisableTiming);
        cudaEventCreateWithFlags(&join, cudaEventDisableTiming);
    }
};

extern "C" void kernel_launch(void* const* d_in, const int* in_sizes, int n_in,
                              void* d_out, int out_size)
{
    static Aux aux;   // one-time stream/event creation (first call is uncaptured)

    const float* x    = (const float*)d_in[0];
    const int*   ei   = (const int*)d_in[1];
    const float* W1l  = (const float*)d_in[2];
    const float* b1   = (const float*)d_in[3];
    const float* W1r  = (const float*)d_in[4];
    const float* W2l  = (const float*)d_in[5];
    const float* b2   = (const float*)d_in[6];
    const float* W2r  = (const float*)d_in[7];
    float*       out  = (float*)d_out;

    const int n_nodes = in_sizes[0] / IN_C;
    const int n_edges = in_sizes[1] / 2;
    const int nchunks = (n_nodes + SCAN_CHUNK - 1) / SCAN_CHUNK;

    const int* src = ei;
    const int* dst = ei + n_edges;

    float *agg1, *hw;
    int *deg, *rowptr, *cursor, *col, *chunkSum;
    cudaGetSymbolAddress((void**)&agg1,     g_agg1);
    cudaGetSymbolAddress((void**)&hw,       g_hw);
    cudaGetSymbolAddress((void**)&deg,      g_deg);
    cudaGetSymbolAddress((void**)&rowptr,   g_rowptr);
    cudaGetSymbolAddress((void**)&cursor,   g_cursor);
    cudaGetSymbolAddress((void**)&col,      g_col);
    cudaGetSymbolAddress((void**)&chunkSum, g_chunkSum);

    const int warps  = (n_edges + 31) / 32;
    const int blocks_sc = (warps * 32 + 255) / 256;

    // ---- fork: stream B does layer-1 scatter while we build CSR ----
    cudaEventRecord(aux.fork, 0);
    cudaStreamWaitEvent(aux.s, aux.fork, 0);

    cudaMemsetAsync(agg1, 0, (size_t)n_nodes * IN_C * sizeof(float), aux.s);
    scatter32<<<blocks_sc, 256, 0, aux.s>>>(x, ei, agg1, n_edges);
    cudaEventRecord(aux.join, aux.s);

    // ---- default stream: CSR build ----
    cudaMemsetAsync(deg, 0, (size_t)n_nodes * sizeof(int));
    deg_count<<<(n_edges + 255) / 256, 256>>>(dst, deg, n_edges);
    scan1<<<nchunks, 256>>>(deg, rowptr, chunkSum, n_nodes);
    scan2b<<<(n_nodes + 255) / 256, 256>>>(rowptr, cursor, chunkSum, n_nodes, nchunks);
    csr_fill<<<(n_edges + 255) / 256, 256>>>(src, dst, cursor, col, n_edges);

    // ---- join ----
    cudaStreamWaitEvent(0, aux.join, 0);

    // Tiled fused transform -> hw, out(=b2+hr)
    {
        const int smem_bytes = (HID_C * STRIDE + 2 * IN_C * HID_C
                              + HID_C * 64 + HID_C + OUT_C) * (int)sizeof(float);
        static bool attr_set = false;
        if (!attr_set) {
            cudaFuncSetAttribute(transform_l1_tiled,
                                 cudaFuncAttributeMaxDynamicSharedMemorySize,
                                 smem_bytes);
            attr_set = true;
        }
        int blocks = (n_nodes + NT - 1) / NT;
        transform_l1_tiled<<<blocks, 256, smem_bytes>>>(
            x, agg1, rowptr, W1l, b1, W1r, W2l, b2, W2r, hw, out, n_nodes);
    }

    // Layer 2: fused gather + final combine
    {
        int gather_blocks = (n_nodes * 32 + 255) / 256;
        gather32_fused<<<gather_blocks, 256>>>(hw, rowptr, col, out, n_nodes);
    }
}

// round 15
// speedup vs baseline: 1.1033x; 1.1033x over previous
#include <cuda_runtime.h>
#include <cstdint>

#define MAX_NODES 100000
#define MAX_EDGES 1600000
#define IN_C  32
#define HID_C 64
#define OUT_C 32
#define NT 128
#define STRIDE 132
#define SCAN_CHUNK 1024
#define MAX_CHUNKS 128

// Scratch (__device__ globals: allocation-free rule)
__device__ __align__(16) float g_agg1[MAX_NODES * IN_C];   // raw sums
__device__ __align__(16) float g_hw  [MAX_NODES * OUT_C];  // relu(h) @ W2_l
__device__ int g_deg   [MAX_NODES];
__device__ int g_rowptr[MAX_NODES + 1];
__device__ int g_rank  [MAX_EDGES];
__device__ int g_col   [MAX_EDGES];
__device__ int g_chunkSum[MAX_CHUNKS];

// ---------------------------------------------------------------------------
// Packed f32x2 helpers (Blackwell FFMA2)
// ---------------------------------------------------------------------------
__device__ __forceinline__ void fma2(unsigned long long& d,
                                     unsigned long long a,
                                     unsigned long long b)
{
    asm("fma.rn.f32x2 %0, %1, %2, %0;" : "+l"(d) : "l"(a), "l"(b));
}
__device__ __forceinline__ unsigned long long pack2(float v)
{
    unsigned long long r;
    asm("mov.b64 %0, {%1, %1};" : "=l"(r) : "r"(__float_as_uint(v)));
    return r;
}
__device__ __forceinline__ float2 unpack2(unsigned long long v)
{
    float2 f;
    asm("mov.b64 {%0, %1}, %2;" : "=f"(f.x), "=f"(f.y) : "l"(v));
    return f;
}

// ---------------------------------------------------------------------------
// CSR build step 1: degree histogram; atomic return = edge's rank in its
// dst group (removes ALL atomics from the fill pass).
// ---------------------------------------------------------------------------
__global__ void deg_count_rank(const int* __restrict__ dst,
                               int* __restrict__ deg,
                               int* __restrict__ rank,
                               int n_edges)
{
    int e = blockIdx.x * blockDim.x + threadIdx.x;
    if (e < n_edges) rank[e] = atomicAdd(&deg[dst[e]], 1);
}

// CSR step 2a: per-chunk exclusive scan. 256 thr x 4 elems.
__global__ void scan1(const int* __restrict__ deg, int* __restrict__ pref,
                      int* __restrict__ chunkSum, int n)
{
    __shared__ int sT[256];
    int chunk = blockIdx.x;
    int base  = chunk * SCAN_CHUNK;
    int t     = threadIdx.x;

    int v[4], s = 0;
#pragma unroll
    for (int j = 0; j < 4; j++) {
        int idx = base + t * 4 + j;
        v[j] = (idx < n) ? deg[idx] : 0;
        s += v[j];
    }
    sT[t] = s;
    __syncthreads();
#pragma unroll
    for (int off = 1; off < 256; off <<= 1) {
        int y = (t >= off) ? sT[t - off] : 0;
        __syncthreads();
        sT[t] += y;
        __syncthreads();
    }
    int excl = sT[t] - s;
#pragma unroll
    for (int j = 0; j < 4; j++) {
        int idx = base + t * 4 + j;
        if (idx < n) pref[idx] = excl;
        excl += v[j];
    }
    if (t == 255) chunkSum[chunk] = sT[255];
}

// CSR step 2b: add chunk offsets via parallel Hillis-Steele over chunk sums
// (R13's per-thread serial loop over <=98 chunks was 4.9us).
__global__ void scan2b(int* __restrict__ rowptr,
                       const int* __restrict__ chunkSum, int n, int nchunks)
{
    __shared__ int sOff[MAX_CHUNKS];
    int t = threadIdx.x;
    if (t < nchunks) sOff[t] = chunkSum[t];
    __syncthreads();
#pragma unroll
    for (int off = 1; off < MAX_CHUNKS; off <<= 1) {
        int v = (t >= off && t < nchunks) ? sOff[t - off] : 0;
        __syncthreads();
        if (t < nchunks) sOff[t] += v;
        __syncthreads();
    }
    // sOff is now INCLUSIVE prefix of chunkSum

    int i = blockIdx.x * blockDim.x + t;
    if (i < n) {
        int myChunk = i / SCAN_CHUNK;
        int off = (myChunk == 0) ? 0 : sOff[myChunk - 1];
        rowptr[i] += off;
    }
    if (i == 0) rowptr[n] = sOff[nchunks - 1];
}

// CSR step 3: atomic-free fill using precomputed ranks (pure streaming).
__global__ void csr_fill_rank(const int* __restrict__ src,
                              const int* __restrict__ dst,
                              const int* __restrict__ rank,
                              const int* __restrict__ rowptr,
                              int* __restrict__ col,
                              int n_edges)
{
    int e = blockIdx.x * blockDim.x + threadIdx.x;
    if (e >= n_edges) return;
    col[rowptr[dst[e]] + rank[e]] = src[e];
}

// ---------------------------------------------------------------------------
// CSR gather, C=32: one warp per node; 8 edges/iter; shfl reduce; no atomics.
//   FUSE_OUT=false: outp[n,:] = raw sum
//   FUSE_OUT=true : outp[n,:] = sum/max(deg,1) + outp[n,:]  (out pre-init b2+hr)
// ---------------------------------------------------------------------------
template <bool FUSE_OUT>
__global__ __launch_bounds__(256)
void gather32(const float* __restrict__ feat,
              const int* __restrict__ rowptr,
              const int* __restrict__ col,
              float* __restrict__ outp,
              int n_nodes)
{
    int node = (blockIdx.x * blockDim.x + threadIdx.x) >> 5;
    int lane = threadIdx.x & 31;
    if (node >= n_nodes) return;

    int beg = rowptr[node];
    int end = rowptr[node + 1];

    int sub = lane >> 3;
    int seg = lane & 7;

    float4 acc = {0.f, 0.f, 0.f, 0.f};
    for (int i = beg; i < end; i += 8) {
        int cv = (lane < 8 && i + lane < end) ? __ldg(col + i + lane) : 0;
        int c0 = __shfl_sync(0xffffffffu, cv, sub);
        int c1 = __shfl_sync(0xffffffffu, cv, 4 + sub);
        bool p0 = (i + sub) < end;
        bool p1 = (i + 4 + sub) < end;
        float4 v0 = {0,0,0,0}, v1 = {0,0,0,0};
        if (p0) v0 = *(const float4*)(feat + (long long)c0 * 32 + seg * 4);
        if (p1) v1 = *(const float4*)(feat + (long long)c1 * 32 + seg * 4);
        acc.x += v0.x + v1.x; acc.y += v0.y + v1.y;
        acc.z += v0.z + v1.z; acc.w += v0.w + v1.w;
    }
#pragma unroll
    for (int off = 8; off < 32; off <<= 1) {
        acc.x += __shfl_xor_sync(0xffffffffu, acc.x, off);
        acc.y += __shfl_xor_sync(0xffffffffu, acc.y, off);
        acc.z += __shfl_xor_sync(0xffffffffu, acc.z, off);
        acc.w += __shfl_xor_sync(0xffffffffu, acc.w, off);
    }
    if (lane < 8) {
        float* dstp = outp + (long long)node * 32 + seg * 4;
        if (FUSE_OUT) {
            float inv = 1.0f / fmaxf((float)(end - beg), 1.0f);
            float4 prev = *(const float4*)dstp;
            float4 o;
            o.x = acc.x * inv + prev.x;
            o.y = acc.y * inv + prev.y;
            o.z = acc.z * inv + prev.z;
            o.w = acc.w * inv + prev.w;
            *(float4*)dstp = o;
        } else {
            *(float4*)dstp = acc;
        }
    }
}

// ---------------------------------------------------------------------------
// Tiled fused transform (R11/R13 structure; deg from rowptr)
// ---------------------------------------------------------------------------
__global__ __launch_bounds__(256)
void transform_l1_tiled(const float* __restrict__ x,
                        const float* __restrict__ agg,
                        const int* __restrict__ rowptr,
                        const float* __restrict__ W1l,
                        const float* __restrict__ b1,
                        const float* __restrict__ W1r,
                        const float* __restrict__ W2l,
                        const float* __restrict__ b2,
                        const float* __restrict__ W2r,
                        float* __restrict__ hw,
                        float* __restrict__ outp,
                        int n_nodes)
{
    extern __shared__ __align__(16) float smem[];
    float* sAgg = smem;
    float* sX   = smem + IN_C * STRIDE;
    float* sH   = smem;                          // overlay
    float* sW1l = smem + HID_C * STRIDE;
    float* sW1r = sW1l + IN_C * HID_C;
    float* sW2  = sW1r + IN_C * HID_C;           // [W2l | W2r]
    float* sB   = sW2  + HID_C * 64;
    float* sB2  = sB   + HID_C;

    int tid  = threadIdx.x;
    int warp = tid >> 5;
    int lane = tid & 31;

    for (int i = tid * 4; i < IN_C * HID_C; i += 256 * 4) {
        *(float4*)&sW1l[i] = *(const float4*)&W1l[i];
        *(float4*)&sW1r[i] = *(const float4*)&W1r[i];
    }
    for (int i = tid * 4; i < HID_C * 64; i += 256 * 4) {
        int k = i >> 6, c = i & 63;
        float4 v = (c < 32) ? *(const float4*)&W2l[k * OUT_C + c]
                            : *(const float4*)&W2r[k * OUT_C + (c - 32)];
        *(float4*)&sW2[i] = v;
    }
    if (tid < HID_C) sB[tid] = b1[tid];
    if (tid < OUT_C) sB2[tid] = b2[tid];

    int nodeBase = blockIdx.x * NT;
    for (int i = tid; i < NT * 8; i += 256) {
        int node = i >> 3, kc = i & 7;
        int ng = nodeBase + node;
        float4 a = {0,0,0,0}, xv = {0,0,0,0};
        float inv = 0.0f;
        if (ng < n_nodes) {
            int deg = rowptr[ng + 1] - rowptr[ng];
            inv = 1.0f / fmaxf((float)deg, 1.0f);
            a  = *(const float4*)(agg + (long long)ng * IN_C + kc * 4);
            xv = *(const float4*)(x   + (long long)ng * IN_C + kc * 4);
        }
        int kb = kc * 4;
        sAgg[(kb + 0) * STRIDE + node] = a.x * inv;
        sAgg[(kb + 1) * STRIDE + node] = a.y * inv;
        sAgg[(kb + 2) * STRIDE + node] = a.z * inv;
        sAgg[(kb + 3) * STRIDE + node] = a.w * inv;
        sX  [(kb + 0) * STRIDE + node] = xv.x;
        sX  [(kb + 1) * STRIDE + node] = xv.y;
        sX  [(kb + 2) * STRIDE + node] = xv.z;
        sX  [(kb + 3) * STRIDE + node] = xv.w;
    }
    __syncthreads();

    const int cb = warp * 8;
    const int nb = lane * 4;

    unsigned long long acc[4][4];
#pragma unroll
    for (int n = 0; n < 4; n++)
#pragma unroll
        for (int p = 0; p < 4; p++) acc[n][p] = 0ull;

#pragma unroll
    for (int k = 0; k < IN_C; k++) {
        float4 av = *(const float4*)&sAgg[k * STRIDE + nb];
        float4 xv = *(const float4*)&sX  [k * STRIDE + nb];
        ulonglong2 wl0 = *(const ulonglong2*)&sW1l[k * HID_C + cb];
        ulonglong2 wl1 = *(const ulonglong2*)&sW1l[k * HID_C + cb + 4];
        ulonglong2 wr0 = *(const ulonglong2*)&sW1r[k * HID_C + cb];
        ulonglong2 wr1 = *(const ulonglong2*)&sW1r[k * HID_C + cb + 4];
        float avf[4] = {av.x, av.y, av.z, av.w};
        float xvf[4] = {xv.x, xv.y, xv.z, xv.w};
#pragma unroll
        for (int n = 0; n < 4; n++) {
            unsigned long long a2 = pack2(avf[n]);
            fma2(acc[n][0], a2, wl0.x); fma2(acc[n][1], a2, wl0.y);
            fma2(acc[n][2], a2, wl1.x); fma2(acc[n][3], a2, wl1.y);
            unsigned long long x2 = pack2(xvf[n]);
            fma2(acc[n][0], x2, wr0.x); fma2(acc[n][1], x2, wr0.y);
            fma2(acc[n][2], x2, wr1.x); fma2(acc[n][3], x2, wr1.y);
        }
    }
    __syncthreads();

#pragma unroll
    for (int c = 0; c < 8; c += 2) {
        float2 p0 = unpack2(acc[0][c / 2]);
        float2 p1 = unpack2(acc[1][c / 2]);
        float2 p2 = unpack2(acc[2][c / 2]);
        float2 p3 = unpack2(acc[3][c / 2]);
        float b0 = sB[cb + c], b1v = sB[cb + c + 1];
        float4 v0 = {fmaxf(p0.x + b0, 0.f), fmaxf(p1.x + b0, 0.f),
                     fmaxf(p2.x + b0, 0.f), fmaxf(p3.x + b0, 0.f)};
        float4 v1 = {fmaxf(p0.y + b1v, 0.f), fmaxf(p1.y + b1v, 0.f),
                     fmaxf(p2.y + b1v, 0.f), fmaxf(p3.y + b1v, 0.f)};
        *(float4*)&sH[(cb + c)     * STRIDE + nb] = v0;
        *(float4*)&sH[(cb + c + 1) * STRIDE + nb] = v1;
    }
    __syncthreads();

    unsigned long long acc2[4][4];
#pragma unroll
    for (int n = 0; n < 4; n++)
#pragma unroll
        for (int p = 0; p < 4; p++) acc2[n][p] = 0ull;

#pragma unroll 8
    for (int k = 0; k < HID_C; k++) {
        float4 hv = *(const float4*)&sH[k * STRIDE + nb];
        ulonglong2 w0 = *(const ulonglong2*)&sW2[k * 64 + cb];
        ulonglong2 w1 = *(const ulonglong2*)&sW2[k * 64 + cb + 4];
        float hvf[4] = {hv.x, hv.y, hv.z, hv.w};
#pragma unroll
        for (int n = 0; n < 4; n++) {
            unsigned long long h2 = pack2(hvf[n]);
            fma2(acc2[n][0], h2, w0.x); fma2(acc2[n][1], h2, w0.y);
            fma2(acc2[n][2], h2, w1.x); fma2(acc2[n][3], h2, w1.y);
        }
    }

    bool to_out = (cb >= 32);
    float* basep = to_out ? outp : hw;
    int coff = to_out ? cb - 32 : cb;
    float add[8];
#pragma unroll
    for (int j = 0; j < 8; j++) add[j] = to_out ? sB2[coff + j] : 0.f;
#pragma unroll
    for (int n = 0; n < 4; n++) {
        int node = nodeBase + nb + n;
        if (node < n_nodes) {
            float2 q0 = unpack2(acc2[n][0]);
            float2 q1 = unpack2(acc2[n][1]);
            float2 q2 = unpack2(acc2[n][2]);
            float2 q3 = unpack2(acc2[n][3]);
            float4 o0 = {q0.x + add[0], q0.y + add[1], q1.x + add[2], q1.y + add[3]};
            float4 o1 = {q2.x + add[4], q2.y + add[5], q3.x + add[6], q3.y + add[7]};
            *(float4*)(basep + (long long)node * OUT_C + coff)     = o0;
            *(float4*)(basep + (long long)node * OUT_C + coff + 4) = o1;
        }
    }
}

// ---------------------------------------------------------------------------
// Launch (single stream — R14 lesson: overlap of LTS-bound phases is a wash)
// ---------------------------------------------------------------------------
extern "C" void kernel_launch(void* const* d_in, const int* in_sizes, int n_in,
                              void* d_out, int out_size)
{
    const float* x    = (const float*)d_in[0];
    const int*   ei   = (const int*)d_in[1];     // [2, E] int32
    const float* W1l  = (const float*)d_in[2];
    const float* b1   = (const float*)d_in[3];
    const float* W1r  = (const float*)d_in[4];
    const float* W2l  = (const float*)d_in[5];
    const float* b2   = (const float*)d_in[6];
    const float* W2r  = (const float*)d_in[7];
    float*       out  = (float*)d_out;

    const int n_nodes = in_sizes[0] / IN_C;
    const int n_edges = in_sizes[1] / 2;
    const int nchunks = (n_nodes + SCAN_CHUNK - 1) / SCAN_CHUNK;

    const int* src = ei;
    const int* dst = ei + n_edges;

    float *agg1, *hw;
    int *deg, *rowptr, *rank, *col, *chunkSum;
    cudaGetSymbolAddress((void**)&agg1,     g_agg1);
    cudaGetSymbolAddress((void**)&hw,       g_hw);
    cudaGetSymbolAddress((void**)&deg,      g_deg);
    cudaGetSymbolAddress((void**)&rowptr,   g_rowptr);
    cudaGetSymbolAddress((void**)&rank,     g_rank);
    cudaGetSymbolAddress((void**)&col,      g_col);
    cudaGetSymbolAddress((void**)&chunkSum, g_chunkSum);

    // --- CSR build (rank-based, atomic-free fill) ---
    cudaMemsetAsync(deg, 0, (size_t)n_nodes * sizeof(int));
    deg_count_rank<<<(n_edges + 255) / 256, 256>>>(dst, deg, rank, n_edges);
    scan1<<<nchunks, 256>>>(deg, rowptr, chunkSum, n_nodes);
    scan2b<<<(n_nodes + 255) / 256, 256>>>(rowptr, chunkSum, n_nodes, nchunks);
    csr_fill_rank<<<(n_edges + 255) / 256, 256>>>(src, dst, rank, rowptr, col, n_edges);

    const int gather_blocks = (n_nodes * 32 + 255) / 256;

    // Layer 1 aggregate: raw sums (no memset; gather overwrites)
    gather32<false><<<gather_blocks, 256>>>(x, rowptr, col, agg1, n_nodes);

    // Tiled fused transform -> hw, out(=b2+hr)
    {
        const int smem_bytes = (HID_C * STRIDE + 2 * IN_C * HID_C
                              + HID_C * 64 + HID_C + OUT_C) * (int)sizeof(float);
        static bool attr_set = false;
        if (!attr_set) {
            cudaFuncSetAttribute(transform_l1_tiled,
                                 cudaFuncAttributeMaxDynamicSharedMemorySize,
                                 smem_bytes);
            attr_set = true;
        }
        int blocks = (n_nodes + NT - 1) / NT;
        transform_l1_tiled<<<blocks, 256, smem_bytes>>>(
            x, agg1, rowptr, W1l, b1, W1r, W2l, b2, W2r, hw, out, n_nodes);
    }

    // Layer 2: fused gather + final combine
    gather32<true><<<gather_blocks, 256>>>(hw, rowptr, col, out, n_nodes);
}